// round 6
// baseline (speedup 1.0000x reference)
#include <cuda_runtime.h>
#include <math.h>

#define B_ 8
#define SEQ 2048
#define DM 512
#define NH 8
#define DH 64
#define NL 3
#define UMAX 40
#define LNEPS 1e-5f

// ---------------- scratch (device globals; no allocation allowed) ----------------
__device__ float g_x [B_*SEQ*DM];
__device__ float g_q [B_*SEQ*DM];
__device__ float g_k [B_*SEQ*DM];
__device__ float g_v [B_*SEQ*DM];
__device__ float g_o [B_*SEQ*DM];
__device__ float g_t1[B_*SEQ*DM];
__device__ float g_t2[B_*SEQ*DM];
__device__ float g_M [B_*NH*SEQ];
__device__ int   g_idx[SEQ*UMAX];
__device__ int   g_top[B_*NH*UMAX];
__device__ float g_vm [B_*NH*DH];
__device__ float g_upd[B_*NH*UMAX*DH];
__device__ float g_red[B_*DM];

// ---------------- threefry2x32 (JAX-compatible) ----------------
__host__ __device__ __forceinline__ void tf2x32(unsigned k0, unsigned k1,
                                                unsigned x0, unsigned x1,
                                                unsigned* o0, unsigned* o1) {
    unsigned ks[3] = {k0, k1, k0 ^ k1 ^ 0x1BD11BDAu};
    x0 += ks[0]; x1 += ks[1];
    const int R0[4] = {13,15,26,6};
    const int R1[4] = {17,29,16,24};
    #pragma unroll
    for (int g = 0; g < 5; g++) {
        #pragma unroll
        for (int q = 0; q < 4; q++) {
            int r = (g & 1) ? R1[q] : R0[q];
            x0 += x1;
            x1 = (x1 << r) | (x1 >> (32 - r));
            x1 ^= x0;
        }
        x0 += ks[(g + 1) % 3];
        x1 += ks[(g + 2) % 3] + (unsigned)(g + 1);
    }
    *o0 = x0; *o1 = x1;
}

// Partitionable threefry random_bits (JAX modern default):
// element f -> counter pair (hi32=0, lo32=f); 32-bit draw = o0 ^ o1.
// randint with power-of-two span L: multiplier = 0 -> idx = lower_bits % L,
// where lower_bits uses k2 = foldlike_split(key)[1] (computed on host).
__global__ void idx_kernel(int* __restrict__ idx, int L, int U, unsigned k0, unsigned k1) {
    int f = blockIdx.x * blockDim.x + threadIdx.x;
    if (f >= L * U) return;
    unsigned o0, o1;
    tf2x32(k0, k1, 0u, (unsigned)f, &o0, &o1);
    idx[f] = (int)((o0 ^ o1) % (unsigned)L);
}

// ---------------- token embedding + positional encoding ----------------
__global__ void embed_kernel(const float* __restrict__ xe, const float* __restrict__ tw,
                             float* __restrict__ out) {
    int i = blockIdx.x * blockDim.x + threadIdx.x;
    if (i >= B_ * SEQ * DM) return;
    int c = i % DM;
    int l = (i / DM) % SEQ;
    int b = i / (DM * SEQ);
    int lm = (l == 0) ? SEQ - 1 : l - 1;
    int lp = (l == SEQ - 1) ? 0 : l + 1;
    float v = tw[c*3+0]*xe[b*SEQ+lm] + tw[c*3+1]*xe[b*SEQ+l] + tw[c*3+2]*xe[b*SEQ+lp];
    int i2 = c >> 1;
    float div = expf((float)(2*i2) * (-9.210340371976184f / 512.0f));
    float arg = (float)l * div;
    v += (c & 1) ? cosf(arg) : sinf(arg);
    out[i] = v;
}

// ---------------- SGEMM: C[m,n] = sum_k A[m,k]*W[n,k] + bias[n]; act=1 -> exact gelu ----------------
__global__ __launch_bounds__(256) void gemm_kernel(
    const float* __restrict__ A, const float* __restrict__ W,
    const float* __restrict__ bias, float* __restrict__ C,
    int M, int N, int K, int act)
{
    __shared__ float As[16][64];
    __shared__ float Ws[16][64];
    int bm = blockIdx.y * 64, bn = blockIdx.x * 64;
    int tid = threadIdx.x;
    int tx = tid & 15, ty = tid >> 4;
    int lr = tid >> 2, lc = (tid & 3) << 2;
    float acc[4][4] = {};
    for (int k0 = 0; k0 < K; k0 += 16) {
        float4 a4 = *(const float4*)(A + (size_t)(bm + lr) * K + k0 + lc);
        float4 w4 = *(const float4*)(W + (size_t)(bn + lr) * K + k0 + lc);
        As[lc+0][lr] = a4.x; As[lc+1][lr] = a4.y; As[lc+2][lr] = a4.z; As[lc+3][lr] = a4.w;
        Ws[lc+0][lr] = w4.x; Ws[lc+1][lr] = w4.y; Ws[lc+2][lr] = w4.z; Ws[lc+3][lr] = w4.w;
        __syncthreads();
        #pragma unroll
        for (int kk = 0; kk < 16; kk++) {
            float4 av = *(const float4*)&As[kk][ty << 2];
            float4 wv = *(const float4*)&Ws[kk][tx << 2];
            float a[4] = {av.x, av.y, av.z, av.w};
            float w[4] = {wv.x, wv.y, wv.z, wv.w};
            #pragma unroll
            for (int i = 0; i < 4; i++)
                #pragma unroll
                for (int j = 0; j < 4; j++)
                    acc[i][j] += a[i] * w[j];
        }
        __syncthreads();
    }
    #pragma unroll
    for (int i = 0; i < 4; i++) {
        int m = bm + (ty << 2) + i;
        #pragma unroll
        for (int j = 0; j < 4; j++) {
            int n = bn + (tx << 2) + j;
            float v = acc[i][j] + bias[n];
            if (act) v = 0.5f * v * (1.0f + erff(v * 0.7071067811865475f));
            C[(size_t)m * N + n] = v;
        }
    }
}

// ---------------- distil conv as GEMM (K=3*DM, circular pad) + BN-affine + ELU ----------------
__global__ __launch_bounds__(256) void convgemm_kernel(
    const float* __restrict__ X, const float* __restrict__ Wc,
    const float* __restrict__ cb, const float* __restrict__ gg,
    const float* __restrict__ be, float* __restrict__ C, int L)
{
    __shared__ float As[16][64];
    __shared__ float Ws[16][64];
    int bm = blockIdx.y * 64, bn = blockIdx.x * 64;
    int tid = threadIdx.x;
    int tx = tid & 15, ty = tid >> 4;
    int lr = tid >> 2, lc = (tid & 3) << 2;
    int m = bm + lr;
    int b = m / L, l = m % L;
    float acc[4][4] = {};
    for (int k0 = 0; k0 < 3 * DM; k0 += 16) {
        int kk = k0 + lc;
        int j = kk / DM;
        int i0 = kk - j * DM;
        int ls = l - 1 + j;
        if (ls < 0) ls += L; else if (ls >= L) ls -= L;
        float4 a4 = *(const float4*)(X + (size_t)(b * L + ls) * DM + i0);
        As[lc+0][lr] = a4.x; As[lc+1][lr] = a4.y; As[lc+2][lr] = a4.z; As[lc+3][lr] = a4.w;
        int n = bn + lr;
        Ws[lc+0][lr] = Wc[((size_t)n * DM + i0 + 0) * 3 + j];
        Ws[lc+1][lr] = Wc[((size_t)n * DM + i0 + 1) * 3 + j];
        Ws[lc+2][lr] = Wc[((size_t)n * DM + i0 + 2) * 3 + j];
        Ws[lc+3][lr] = Wc[((size_t)n * DM + i0 + 3) * 3 + j];
        __syncthreads();
        #pragma unroll
        for (int kk2 = 0; kk2 < 16; kk2++) {
            float4 av = *(const float4*)&As[kk2][ty << 2];
            float4 wv = *(const float4*)&Ws[kk2][tx << 2];
            float a[4] = {av.x, av.y, av.z, av.w};
            float w[4] = {wv.x, wv.y, wv.z, wv.w};
            #pragma unroll
            for (int i = 0; i < 4; i++)
                #pragma unroll
                for (int jj = 0; jj < 4; jj++)
                    acc[i][jj] += a[i] * w[jj];
        }
        __syncthreads();
    }
    const float invs = 0.9999950000374997f; // 1/sqrt(1+1e-5)
    #pragma unroll
    for (int i = 0; i < 4; i++) {
        int mm = bm + (ty << 2) + i;
        #pragma unroll
        for (int j = 0; j < 4; j++) {
            int n = bn + (tx << 2) + j;
            float v = (acc[i][j] + cb[n]) * invs * gg[n] + be[n];
            v = v > 0.0f ? v : expm1f(v);
            C[(size_t)mm * DM + n] = v;
        }
    }
}

// maxpool kernel=3 stride=2 pad=1 (-inf identity) along L
__global__ void pool_kernel(const float* __restrict__ Y, float* __restrict__ X, int Lin) {
    int Lout = Lin >> 1;
    int i = blockIdx.x * blockDim.x + threadIdx.x;
    if (i >= B_ * Lout * DM) return;
    int c = i % DM;
    int lp = (i / DM) % Lout;
    int b = i / (DM * Lout);
    float mv = -INFINITY;
    #pragma unroll
    for (int j = 0; j < 3; j++) {
        int l = 2 * lp - 1 + j;
        if (l >= 0 && l < Lin) mv = fmaxf(mv, Y[(size_t)(b * Lin + l) * DM + c]);
    }
    X[(size_t)(b * Lout + lp) * DM + c] = mv;
}

// ---------------- sparsity measure M[b,h,l] = max_u qk - mean_u qk ----------------
__global__ void m_kernel(const float* __restrict__ q, const float* __restrict__ k,
                         const int* __restrict__ idx, float* __restrict__ Mout,
                         int L, int U) {
    int wid = (blockIdx.x * blockDim.x + threadIdx.x) >> 5;
    int lane = threadIdx.x & 31;
    if (wid >= B_ * NH * L) return;
    int l = wid % L;
    int bh = wid / L;
    int h = bh % NH, b = bh / NH;
    const float* qp = q + (size_t)(b * L + l) * DM + h * DH;
    float q0 = qp[lane], q1 = qp[lane + 32];
    float mx = -INFINITY, sum = 0.0f;
    for (int u = 0; u < U; u++) {
        int ki = idx[l * U + u];
        const float* kp = k + (size_t)(b * L + ki) * DM + h * DH;
        float p = q0 * kp[lane] + q1 * kp[lane + 32];
        #pragma unroll
        for (int off = 16; off; off >>= 1) p += __shfl_xor_sync(0xffffffffu, p, off);
        mx = fmaxf(mx, p);
        sum += p;
    }
    if (lane == 0) Mout[bh * L + l] = mx - sum / (float)U;
}

// ---------------- top-U selection (value desc, tie -> smaller index) ----------------
__global__ void topk_kernel(const float* __restrict__ Mv, int* __restrict__ top, int L, int U) {
    __shared__ float sm[2048];
    __shared__ float rv[256];
    __shared__ int   ri[256];
    int bh = blockIdx.x, tid = threadIdx.x;
    const float* row = Mv + bh * L;
    for (int l = tid; l < L; l += 256) sm[l] = row[l];
    __syncthreads();
    for (int it = 0; it < U; it++) {
        float bv = -INFINITY; int bi = 0x7fffffff;
        for (int l = tid; l < L; l += 256) {
            float v = sm[l];
            if (v > bv || (v == bv && l < bi)) { bv = v; bi = l; }
        }
        rv[tid] = bv; ri[tid] = bi;
        __syncthreads();
        for (int s = 128; s > 0; s >>= 1) {
            if (tid < s) {
                if (rv[tid+s] > rv[tid] || (rv[tid+s] == rv[tid] && ri[tid+s] < ri[tid])) {
                    rv[tid] = rv[tid+s]; ri[tid] = ri[tid+s];
                }
            }
            __syncthreads();
        }
        if (tid == 0) { top[bh * U + it] = ri[0]; sm[ri[0]] = -INFINITY; }
        __syncthreads();
    }
}

__global__ void vmean_kernel(const float* __restrict__ v, float* __restrict__ vm, int L) {
    int bh = blockIdx.x, d = threadIdx.x;
    int h = bh % NH, b = bh / NH;
    float acc = 0.0f;
    for (int l = 0; l < L; l++) acc += v[(size_t)(b * L + l) * DM + h * DH + d];
    vm[bh * DH + d] = acc / (float)L;
}

// ---------------- full softmax attention for the U selected queries ----------------
__global__ void attn_kernel(const float* __restrict__ q, const float* __restrict__ k,
                            const float* __restrict__ v, const int* __restrict__ top,
                            float* __restrict__ upd, int L, int U) {
    __shared__ float qs[64];
    __shared__ float s[2048];
    __shared__ float red[128];
    int bhu = blockIdx.x;
    int u = bhu % U;
    int bh = bhu / U;
    int h = bh % NH, b = bh / NH;
    int tid = threadIdx.x; // 128
    int lq = top[bh * U + u];
    if (tid < 64) qs[tid] = q[(size_t)(b * L + lq) * DM + h * DH + tid];
    __syncthreads();
    float lmax = -INFINITY;
    const float4* qs4 = (const float4*)qs;
    for (int l = tid; l < L; l += 128) {
        const float4* kp4 = (const float4*)(k + (size_t)(b * L + l) * DM + h * DH);
        float acc = 0.0f;
        #pragma unroll
        for (int d4 = 0; d4 < 16; d4++) {
            float4 kk = kp4[d4], qq = qs4[d4];
            acc += qq.x*kk.x + qq.y*kk.y + qq.z*kk.z + qq.w*kk.w;
        }
        acc *= 0.125f;
        s[l] = acc;
        lmax = fmaxf(lmax, acc);
    }
    red[tid] = lmax; __syncthreads();
    for (int st = 64; st; st >>= 1) { if (tid < st) red[tid] = fmaxf(red[tid], red[tid+st]); __syncthreads(); }
    float mx = red[0]; __syncthreads();
    float lsum = 0.0f;
    for (int l = tid; l < L; l += 128) { float e = expf(s[l] - mx); s[l] = e; lsum += e; }
    red[tid] = lsum; __syncthreads();
    for (int st = 64; st; st >>= 1) { if (tid < st) red[tid] += red[tid+st]; __syncthreads(); }
    float ssum = red[0]; __syncthreads();
    int d = tid & 63, half = tid >> 6;
    int l0 = half * (L >> 1), l1 = l0 + (L >> 1);
    float acc = 0.0f;
    for (int l = l0; l < l1; l++) acc += s[l] * v[(size_t)(b * L + l) * DM + h * DH + d];
    red[tid] = acc; __syncthreads();
    if (tid < 64) upd[(size_t)(bh * U + u) * DH + tid] = (red[tid] + red[tid + 64]) / ssum;
}

__global__ void oinit_kernel(float* __restrict__ o, const float* __restrict__ vm, int L) {
    int i = blockIdx.x * blockDim.x + threadIdx.x;
    if (i >= B_ * L * DM) return;
    int c = i % DM;
    int b = i / (DM * L);
    o[i] = vm[(b * NH + (c >> 6)) * DH + (c & 63)];
}

__global__ void scatter_kernel(float* __restrict__ o, const float* __restrict__ upd,
                               const int* __restrict__ top, int L, int U) {
    int bhu = blockIdx.x, d = threadIdx.x;
    int u = bhu % U;
    int bh = bhu / U;
    int h = bh % NH, b = bh / NH;
    int l = top[bh * U + u];
    o[(size_t)(b * L + l) * DM + h * DH + d] = upd[(size_t)(bh * U + u) * DH + d];
}

// ---------------- x = LayerNorm(x + t) (t may be null) ----------------
__global__ void addln_kernel(float* __restrict__ x, const float* __restrict__ t,
                             const float* __restrict__ g, const float* __restrict__ bb) {
    __shared__ float row[512];
    __shared__ float red[256];
    size_t r = blockIdx.x;
    int tid = threadIdx.x;
    float v0 = x[r * 512 + tid]       + (t ? t[r * 512 + tid]       : 0.0f);
    float v1 = x[r * 512 + tid + 256] + (t ? t[r * 512 + tid + 256] : 0.0f);
    row[tid] = v0; row[tid + 256] = v1;
    red[tid] = v0 + v1;
    __syncthreads();
    for (int s = 128; s; s >>= 1) { if (tid < s) red[tid] += red[tid + s]; __syncthreads(); }
    float mu = red[0] * (1.0f / 512.0f);
    __syncthreads();
    float d0 = row[tid] - mu, d1 = row[tid + 256] - mu;
    red[tid] = d0 * d0 + d1 * d1;
    __syncthreads();
    for (int s = 128; s; s >>= 1) { if (tid < s) red[tid] += red[tid + s]; __syncthreads(); }
    float rstd = rsqrtf(red[0] * (1.0f / 512.0f) + LNEPS);
    x[r * 512 + tid]       = d0 * rstd * g[tid]       + bb[tid];
    x[r * 512 + tid + 256] = d1 * rstd * g[tid + 256] + bb[tid + 256];
}

__global__ void rowmax_kernel(const float* __restrict__ x, float* __restrict__ outr, int L) {
    int b = blockIdx.x, c = threadIdx.x; // 512 threads
    float m = -INFINITY;
    for (int l = 0; l < L; l++) m = fmaxf(m, x[(size_t)(b * L + l) * DM + c]);
    outr[b * DM + c] = m;
}

__global__ void proj_kernel(const float* __restrict__ red, const float* __restrict__ pw,
                            const float* __restrict__ pb, float* __restrict__ out) {
    int w = threadIdx.x >> 5, lane = threadIdx.x & 31; // 16 warps
    int b = w >> 1, o = w & 1;
    float acc = 0.0f;
    for (int c = lane; c < DM; c += 32) acc += red[b * DM + c] * pw[o * DM + c];
    #pragma unroll
    for (int s = 16; s; s >>= 1) acc += __shfl_xor_sync(0xffffffffu, acc, s);
    if (lane == 0) out[b * 2 + o] = acc + pb[o];
}

// ---------------- host ----------------
extern "C" void kernel_launch(void* const* d_in, const int* in_sizes, int n_in,
                              void* d_out, int out_size) {
    (void)n_in; (void)out_size;
    const float* x_enc = (const float*)d_in[0];
    const float* tok_w = (const float*)d_in[1];
    const float *Wq, *Wk, *Wv, *Wo, *bq, *bk, *bv, *bo;
    if (in_sizes[5] > 10000) { // dict order: Wq,Wk,Wv,Wo,bq,bk,bv,bo
        Wq = (const float*)d_in[2]; Wk = (const float*)d_in[3];
        Wv = (const float*)d_in[4]; Wo = (const float*)d_in[5];
        bq = (const float*)d_in[6]; bk = (const float*)d_in[7];
        bv = (const float*)d_in[8]; bo = (const float*)d_in[9];
    } else {                   // signature order: Wq,Wk,Wv,bq,bk,bv,Wo,bo
        Wq = (const float*)d_in[2]; Wk = (const float*)d_in[3];
        Wv = (const float*)d_in[4]; bq = (const float*)d_in[5];
        bk = (const float*)d_in[6]; bv = (const float*)d_in[7];
        Wo = (const float*)d_in[8]; bo = (const float*)d_in[9];
    }
    const float* W1   = (const float*)d_in[10];
    const float* b1   = (const float*)d_in[11];
    const float* W2   = (const float*)d_in[12];
    const float* b2   = (const float*)d_in[13];
    const float* ln1g = (const float*)d_in[14];
    const float* ln1b = (const float*)d_in[15];
    const float* ln2g = (const float*)d_in[16];
    const float* ln2b = (const float*)d_in[17];
    const float* dcw  = (const float*)d_in[18];
    const float* dcb  = (const float*)d_in[19];
    const float* bng  = (const float*)d_in[20];
    const float* bnb  = (const float*)d_in[21];
    const float* lnfg = (const float*)d_in[22];
    const float* lnfb = (const float*)d_in[23];
    const float* pw   = (const float*)d_in[24];
    const float* pb   = (const float*)d_in[25];

    float *x, *q, *k, *v, *o, *t1, *t2, *Mb, *vm, *upd, *redb;
    int *idxb, *topb;
    cudaGetSymbolAddress((void**)&x,   g_x);
    cudaGetSymbolAddress((void**)&q,   g_q);
    cudaGetSymbolAddress((void**)&k,   g_k);
    cudaGetSymbolAddress((void**)&v,   g_v);
    cudaGetSymbolAddress((void**)&o,   g_o);
    cudaGetSymbolAddress((void**)&t1,  g_t1);
    cudaGetSymbolAddress((void**)&t2,  g_t2);
    cudaGetSymbolAddress((void**)&Mb,  g_M);
    cudaGetSymbolAddress((void**)&vm,  g_vm);
    cudaGetSymbolAddress((void**)&upd, g_upd);
    cudaGetSymbolAddress((void**)&redb,g_red);
    cudaGetSymbolAddress((void**)&idxb,g_idx);
    cudaGetSymbolAddress((void**)&topb,g_top);

    embed_kernel<<<(B_*SEQ*DM + 255) / 256, 256>>>(x_enc, tok_w, x);

    int L = SEQ;
    for (int i = 0; i < NL; i++) {
        int Mrows = B_ * L;
        dim3 gg(DM / 64, Mrows / 64);
        gemm_kernel<<<gg, 256>>>(x, Wq + i*DM*DM, bq + i*DM, q, Mrows, DM, DM, 0);
        gemm_kernel<<<gg, 256>>>(x, Wk + i*DM*DM, bk + i*DM, k, Mrows, DM, DM, 0);
        gemm_kernel<<<gg, 256>>>(x, Wv + i*DM*DM, bv + i*DM, v, Mrows, DM, DM, 0);

        // U = min(5*ceil(ln L), L)
        int U = 5 * (int)ceil(log((double)L));
        if (U > L) U = L;

        // Key chain (modern JAX, threefry_partitionable=True):
        //   layer_key = fold_in(key(42), i)        = tf2x32((0,42), (0,i))
        //   (k1, k2)  = foldlike_split(layer_key)  : child_j = tf2x32(layer_key, (0,j))
        //   randint lower_bits use k2 = child 1; multiplier=0 (pow2 span) -> idx = bits(k2) % L
        unsigned f0, f1, c0, c1;
        tf2x32(0u, 42u, 0u, (unsigned)i, &f0, &f1);
        tf2x32(f0, f1, 0u, 1u, &c0, &c1);   // split child 1

        idx_kernel<<<(L*U + 255) / 256, 256>>>(idxb, L, U, c0, c1);
        m_kernel<<<(B_*NH*L*32 + 127) / 128, 128>>>(q, k, idxb, Mb, L, U);
        topk_kernel<<<B_*NH, 256>>>(Mb, topb, L, U);
        vmean_kernel<<<B_*NH, 64>>>(v, vm, L);
        attn_kernel<<<B_*NH*U, 128>>>(q, k, v, topb, upd, L, U);
        oinit_kernel<<<(B_*L*DM + 255) / 256, 256>>>(o, vm, L);
        scatter_kernel<<<B_*NH*U, 64>>>(o, upd, topb, L, U);

        gemm_kernel<<<gg, 256>>>(o, Wo + i*DM*DM, bo + i*DM, t1, Mrows, DM, DM, 0);
        addln_kernel<<<Mrows, 256>>>(x, t1, ln1g + i*DM, ln1b + i*DM);
        gemm_kernel<<<gg, 256>>>(x, W1 + i*DM*DM, b1 + i*DM, t1, Mrows, DM, DM, 1);
        gemm_kernel<<<gg, 256>>>(t1, W2 + i*DM*DM, b2 + i*DM, t2, Mrows, DM, DM, 0);
        addln_kernel<<<Mrows, 256>>>(x, t2, ln2g + i*DM, ln2b + i*DM);

        if (i < NL - 1) {
            convgemm_kernel<<<gg, 256>>>(x, dcw + (size_t)i*DM*DM*3, dcb + i*DM,
                                         bng + i*DM, bnb + i*DM, t1, L);
            int Lout = L / 2;
            pool_kernel<<<(B_*Lout*DM + 255) / 256, 256>>>(t1, x, L);
            L = Lout;
        }
    }

    addln_kernel<<<B_*L, 256>>>(x, (const float*)nullptr, lnfg, lnfb);
    rowmax_kernel<<<B_, 512>>>(x, redb, L);
    proj_kernel<<<1, 512>>>(redb, pw, pb, (float*)d_out);
}

// round 8
// speedup vs baseline: 1.2632x; 1.2632x over previous
#include <cuda_runtime.h>
#include <math.h>

#define B_ 8
#define SEQ 2048
#define DM 512
#define NH 8
#define DH 64
#define NL 3
#define UMAX 40
#define LNEPS 1e-5f

// ---------------- scratch (device globals; no allocation allowed) ----------------
__device__ float g_x [B_*SEQ*DM];
__device__ float g_q [B_*SEQ*DM];
__device__ float g_k [B_*SEQ*DM];
__device__ float g_v [B_*SEQ*DM];
__device__ float g_o [B_*SEQ*DM];
__device__ float g_t1[B_*SEQ*DM];
__device__ float g_t2[B_*SEQ*DM];
__device__ float g_M [B_*NH*SEQ];
__device__ int   g_idx[SEQ*UMAX];
__device__ int   g_top[B_*NH*UMAX];
__device__ float g_vm [B_*NH*DH];
__device__ float g_upd[B_*NH*UMAX*DH];
__device__ float g_red[B_*DM];

// ---------------- threefry2x32 (JAX-compatible) ----------------
__host__ __device__ __forceinline__ void tf2x32(unsigned k0, unsigned k1,
                                                unsigned x0, unsigned x1,
                                                unsigned* o0, unsigned* o1) {
    unsigned ks[3] = {k0, k1, k0 ^ k1 ^ 0x1BD11BDAu};
    x0 += ks[0]; x1 += ks[1];
    const int R0[4] = {13,15,26,6};
    const int R1[4] = {17,29,16,24};
    #pragma unroll
    for (int g = 0; g < 5; g++) {
        #pragma unroll
        for (int q = 0; q < 4; q++) {
            int r = (g & 1) ? R1[q] : R0[q];
            x0 += x1;
            x1 = (x1 << r) | (x1 >> (32 - r));
            x1 ^= x0;
        }
        x0 += ks[(g + 1) % 3];
        x1 += ks[(g + 2) % 3] + (unsigned)(g + 1);
    }
    *o0 = x0; *o1 = x1;
}

// Partitionable threefry random_bits: element f -> counter (0, f); draw = o0 ^ o1.
// randint pow2 span: idx = bits(k2) % L, k2 = foldlike_split(key)[1] (host-side).
__global__ void idx_kernel(int* __restrict__ idx, int L, int U, unsigned k0, unsigned k1) {
    int f = blockIdx.x * blockDim.x + threadIdx.x;
    if (f >= L * U) return;
    unsigned o0, o1;
    tf2x32(k0, k1, 0u, (unsigned)f, &o0, &o1);
    idx[f] = (int)((o0 ^ o1) % (unsigned)L);
}

// ---------------- token embedding + positional encoding ----------------
__global__ void embed_kernel(const float* __restrict__ xe, const float* __restrict__ tw,
                             float* __restrict__ out) {
    int i = blockIdx.x * blockDim.x + threadIdx.x;
    if (i >= B_ * SEQ * DM) return;
    int c = i % DM;
    int l = (i / DM) % SEQ;
    int b = i / (DM * SEQ);
    int lm = (l == 0) ? SEQ - 1 : l - 1;
    int lp = (l == SEQ - 1) ? 0 : l + 1;
    float v = tw[c*3+0]*xe[b*SEQ+lm] + tw[c*3+1]*xe[b*SEQ+l] + tw[c*3+2]*xe[b*SEQ+lp];
    int i2 = c >> 1;
    float div = expf((float)(2*i2) * (-9.210340371976184f / 512.0f));
    float arg = (float)l * div;
    v += (c & 1) ? cosf(arg) : sinf(arg);
    out[i] = v;
}

// ---------------- SGEMM 128x128 tile, 8x8 microtile ----------------
// C[m,n] = sum_k A[m,k]*W[n,k] + bias[n]; act=1 -> exact gelu
#define SST 132  // padded smem stride (floats); 132*4B is 16B-aligned
__global__ __launch_bounds__(256) void gemm_kernel(
    const float* __restrict__ A, const float* __restrict__ W,
    const float* __restrict__ bias, float* __restrict__ C,
    int M, int N, int K, int act)
{
    __shared__ float As[16][SST];
    __shared__ float Ws[16][SST];
    int bm = blockIdx.y * 128, bn = blockIdx.x * 128;
    int tid = threadIdx.x;
    int tx = tid & 15, ty = tid >> 4;
    int lr = tid >> 2;          // 0..63
    int lc = (tid & 3) << 2;    // 0,4,8,12
    float acc[8][8] = {};
    for (int k0 = 0; k0 < K; k0 += 16) {
        #pragma unroll
        for (int h = 0; h < 2; h++) {
            int row = lr + h * 64;
            float4 a4 = *(const float4*)(A + (size_t)(bm + row) * K + k0 + lc);
            As[lc+0][row] = a4.x; As[lc+1][row] = a4.y; As[lc+2][row] = a4.z; As[lc+3][row] = a4.w;
            float4 w4 = *(const float4*)(W + (size_t)(bn + row) * K + k0 + lc);
            Ws[lc+0][row] = w4.x; Ws[lc+1][row] = w4.y; Ws[lc+2][row] = w4.z; Ws[lc+3][row] = w4.w;
        }
        __syncthreads();
        #pragma unroll
        for (int kk = 0; kk < 16; kk++) {
            float a[8], w[8];
            *(float4*)(a)     = *(const float4*)&As[kk][ty << 2];
            *(float4*)(a + 4) = *(const float4*)&As[kk][64 + (ty << 2)];
            *(float4*)(w)     = *(const float4*)&Ws[kk][tx << 2];
            *(float4*)(w + 4) = *(const float4*)&Ws[kk][64 + (tx << 2)];
            #pragma unroll
            for (int i = 0; i < 8; i++)
                #pragma unroll
                for (int j = 0; j < 8; j++)
                    acc[i][j] += a[i] * w[j];
        }
        __syncthreads();
    }
    #pragma unroll
    for (int i = 0; i < 8; i++) {
        int m = bm + ((i < 4) ? ((ty << 2) + i) : (64 + (ty << 2) + i - 4));
        #pragma unroll
        for (int jh = 0; jh < 2; jh++) {
            int n = bn + jh * 64 + (tx << 2);
            float4 o;
            o.x = acc[i][jh*4+0] + bias[n+0];
            o.y = acc[i][jh*4+1] + bias[n+1];
            o.z = acc[i][jh*4+2] + bias[n+2];
            o.w = acc[i][jh*4+3] + bias[n+3];
            if (act) {
                o.x = 0.5f * o.x * (1.0f + erff(o.x * 0.7071067811865475f));
                o.y = 0.5f * o.y * (1.0f + erff(o.y * 0.7071067811865475f));
                o.z = 0.5f * o.z * (1.0f + erff(o.z * 0.7071067811865475f));
                o.w = 0.5f * o.w * (1.0f + erff(o.w * 0.7071067811865475f));
            }
            *(float4*)(C + (size_t)m * N + n) = o;
        }
    }
}

// ---------------- distil conv as GEMM (K=3*DM, circular pad) + BN-affine + ELU ----------------
__global__ __launch_bounds__(256) void convgemm_kernel(
    const float* __restrict__ X, const float* __restrict__ Wc,
    const float* __restrict__ cb, const float* __restrict__ gg,
    const float* __restrict__ be, float* __restrict__ C, int L)
{
    __shared__ float As[16][SST];
    __shared__ float Ws[16][SST];
    int bm = blockIdx.y * 128, bn = blockIdx.x * 128;
    int tid = threadIdx.x;
    int tx = tid & 15, ty = tid >> 4;
    int lr = tid >> 2;
    int lc = (tid & 3) << 2;
    float acc[8][8] = {};
    for (int k0 = 0; k0 < 3 * DM; k0 += 16) {
        int kk = k0 + lc;
        int j = kk / DM;            // conv tap 0..2 (float4 never crosses tap boundary)
        int i0 = kk - j * DM;
        #pragma unroll
        for (int h = 0; h < 2; h++) {
            int row = lr + h * 64;
            int m = bm + row;
            int b = m / L, l = m % L;
            int ls = l - 1 + j;
            if (ls < 0) ls += L; else if (ls >= L) ls -= L;
            float4 a4 = *(const float4*)(X + (size_t)(b * L + ls) * DM + i0);
            As[lc+0][row] = a4.x; As[lc+1][row] = a4.y; As[lc+2][row] = a4.z; As[lc+3][row] = a4.w;
            int n = bn + row;
            Ws[lc+0][row] = Wc[((size_t)n * DM + i0 + 0) * 3 + j];
            Ws[lc+1][row] = Wc[((size_t)n * DM + i0 + 1) * 3 + j];
            Ws[lc+2][row] = Wc[((size_t)n * DM + i0 + 2) * 3 + j];
            Ws[lc+3][row] = Wc[((size_t)n * DM + i0 + 3) * 3 + j];
        }
        __syncthreads();
        #pragma unroll
        for (int kk2 = 0; kk2 < 16; kk2++) {
            float a[8], w[8];
            *(float4*)(a)     = *(const float4*)&As[kk2][ty << 2];
            *(float4*)(a + 4) = *(const float4*)&As[kk2][64 + (ty << 2)];
            *(float4*)(w)     = *(const float4*)&Ws[kk2][tx << 2];
            *(float4*)(w + 4) = *(const float4*)&Ws[kk2][64 + (tx << 2)];
            #pragma unroll
            for (int i = 0; i < 8; i++)
                #pragma unroll
                for (int jj = 0; jj < 8; jj++)
                    acc[i][jj] += a[i] * w[jj];
        }
        __syncthreads();
    }
    const float invs = 0.9999950000374997f; // 1/sqrt(1+1e-5)
    #pragma unroll
    for (int i = 0; i < 8; i++) {
        int m = bm + ((i < 4) ? ((ty << 2) + i) : (64 + (ty << 2) + i - 4));
        #pragma unroll
        for (int jh = 0; jh < 2; jh++) {
            int n = bn + jh * 64 + (tx << 2);
            float4 o;
            float* po = &o.x;
            #pragma unroll
            for (int c4 = 0; c4 < 4; c4++) {
                float v = (acc[i][jh*4+c4] + cb[n+c4]) * invs * gg[n+c4] + be[n+c4];
                po[c4] = v > 0.0f ? v : expm1f(v);
            }
            *(float4*)(C + (size_t)m * DM + n) = o;
        }
    }
}

// maxpool kernel=3 stride=2 pad=1 (-inf identity) along L
__global__ void pool_kernel(const float* __restrict__ Y, float* __restrict__ X, int Lin) {
    int Lout = Lin >> 1;
    int i = blockIdx.x * blockDim.x + threadIdx.x;
    if (i >= B_ * Lout * DM) return;
    int c = i % DM;
    int lp = (i / DM) % Lout;
    int b = i / (DM * Lout);
    float mv = -INFINITY;
    #pragma unroll
    for (int j = 0; j < 3; j++) {
        int l = 2 * lp - 1 + j;
        if (l >= 0 && l < Lin) mv = fmaxf(mv, Y[(size_t)(b * Lin + l) * DM + c]);
    }
    X[(size_t)(b * Lout + lp) * DM + c] = mv;
}

// ---------------- sparsity measure M[b,h,l] = max_u qk - mean_u qk ----------------
__global__ void m_kernel(const float* __restrict__ q, const float* __restrict__ k,
                         const int* __restrict__ idx, float* __restrict__ Mout,
                         int L, int U) {
    int wid = (blockIdx.x * blockDim.x + threadIdx.x) >> 5;
    int lane = threadIdx.x & 31;
    if (wid >= B_ * NH * L) return;
    int l = wid % L;
    int bh = wid / L;
    int h = bh % NH, b = bh / NH;
    const float* qp = q + (size_t)(b * L + l) * DM + h * DH;
    float q0 = qp[lane], q1 = qp[lane + 32];
    float mx = -INFINITY, sum = 0.0f;
    for (int u = 0; u < U; u++) {
        int ki = idx[l * U + u];
        const float* kp = k + (size_t)(b * L + ki) * DM + h * DH;
        float p = q0 * kp[lane] + q1 * kp[lane + 32];
        #pragma unroll
        for (int off = 16; off; off >>= 1) p += __shfl_xor_sync(0xffffffffu, p, off);
        mx = fmaxf(mx, p);
        sum += p;
    }
    if (lane == 0) Mout[bh * L + l] = mx - sum / (float)U;
}

// ---------------- top-U selection (value desc, tie -> smaller index) ----------------
__global__ void topk_kernel(const float* __restrict__ Mv, int* __restrict__ top, int L, int U) {
    __shared__ float sm[2048];
    __shared__ float rv[256];
    __shared__ int   ri[256];
    int bh = blockIdx.x, tid = threadIdx.x;
    const float* row = Mv + bh * L;
    for (int l = tid; l < L; l += 256) sm[l] = row[l];
    __syncthreads();
    for (int it = 0; it < U; it++) {
        float bv = -INFINITY; int bi = 0x7fffffff;
        for (int l = tid; l < L; l += 256) {
            float v = sm[l];
            if (v > bv || (v == bv && l < bi)) { bv = v; bi = l; }
        }
        rv[tid] = bv; ri[tid] = bi;
        __syncthreads();
        for (int s = 128; s > 0; s >>= 1) {
            if (tid < s) {
                if (rv[tid+s] > rv[tid] || (rv[tid+s] == rv[tid] && ri[tid+s] < ri[tid])) {
                    rv[tid] = rv[tid+s]; ri[tid] = ri[tid+s];
                }
            }
            __syncthreads();
        }
        if (tid == 0) { top[bh * U + it] = ri[0]; sm[ri[0]] = -INFINITY; }
        __syncthreads();
    }
}

__global__ void vmean_kernel(const float* __restrict__ v, float* __restrict__ vm, int L) {
    int bh = blockIdx.x, d = threadIdx.x;
    int h = bh % NH, b = bh / NH;
    float acc = 0.0f;
    for (int l = 0; l < L; l++) acc += v[(size_t)(b * L + l) * DM + h * DH + d];
    vm[bh * DH + d] = acc / (float)L;
}

// ---------------- full softmax attention for the U selected queries ----------------
__global__ void attn_kernel(const float* __restrict__ q, const float* __restrict__ k,
                            const float* __restrict__ v, const int* __restrict__ top,
                            float* __restrict__ upd, int L, int U) {
    __shared__ float qs[64];
    __shared__ float s[2048];
    __shared__ float red[128];
    int bhu = blockIdx.x;
    int u = bhu % U;
    int bh = bhu / U;
    int h = bh % NH, b = bh / NH;
    int tid = threadIdx.x; // 128
    int lq = top[bh * U + u];
    if (tid < 64) qs[tid] = q[(size_t)(b * L + lq) * DM + h * DH + tid];
    __syncthreads();
    float lmax = -INFINITY;
    const float4* qs4 = (const float4*)qs;
    for (int l = tid; l < L; l += 128) {
        const float4* kp4 = (const float4*)(k + (size_t)(b * L + l) * DM + h * DH);
        float acc = 0.0f;
        #pragma unroll
        for (int d4 = 0; d4 < 16; d4++) {
            float4 kk = kp4[d4], qq = qs4[d4];
            acc += qq.x*kk.x + qq.y*kk.y + qq.z*kk.z + qq.w*kk.w;
        }
        acc *= 0.125f;
        s[l] = acc;
        lmax = fmaxf(lmax, acc);
    }
    red[tid] = lmax; __syncthreads();
    for (int st = 64; st; st >>= 1) { if (tid < st) red[tid] = fmaxf(red[tid], red[tid+st]); __syncthreads(); }
    float mx = red[0]; __syncthreads();
    float lsum = 0.0f;
    for (int l = tid; l < L; l += 128) { float e = expf(s[l] - mx); s[l] = e; lsum += e; }
    red[tid] = lsum; __syncthreads();
    for (int st = 64; st; st >>= 1) { if (tid < st) red[tid] += red[tid+st]; __syncthreads(); }
    float ssum = red[0]; __syncthreads();
    int d = tid & 63, half = tid >> 6;
    int l0 = half * (L >> 1), l1 = l0 + (L >> 1);
    float acc = 0.0f;
    for (int l = l0; l < l1; l++) acc += s[l] * v[(size_t)(b * L + l) * DM + h * DH + d];
    red[tid] = acc; __syncthreads();
    if (tid < 64) upd[(size_t)(bh * U + u) * DH + tid] = (red[tid] + red[tid + 64]) / ssum;
}

__global__ void oinit_kernel(float* __restrict__ o, const float* __restrict__ vm, int L) {
    int i = blockIdx.x * blockDim.x + threadIdx.x;
    if (i >= B_ * L * DM) return;
    int c = i % DM;
    int b = i / (DM * L);
    o[i] = vm[(b * NH + (c >> 6)) * DH + (c & 63)];
}

__global__ void scatter_kernel(float* __restrict__ o, const float* __restrict__ upd,
                               const int* __restrict__ top, int L, int U) {
    int bhu = blockIdx.x, d = threadIdx.x;
    int u = bhu % U;
    int bh = bhu / U;
    int h = bh % NH, b = bh / NH;
    int l = top[bh * U + u];
    o[(size_t)(b * L + l) * DM + h * DH + d] = upd[(size_t)(bh * U + u) * DH + d];
}

// ---------------- x = LayerNorm(x + t) (t may be null) ----------------
__global__ void addln_kernel(float* __restrict__ x, const float* __restrict__ t,
                             const float* __restrict__ g, const float* __restrict__ bb) {
    __shared__ float row[512];
    __shared__ float red[256];
    size_t r = blockIdx.x;
    int tid = threadIdx.x;
    float v0 = x[r * 512 + tid]       + (t ? t[r * 512 + tid]       : 0.0f);
    float v1 = x[r * 512 + tid + 256] + (t ? t[r * 512 + tid + 256] : 0.0f);
    row[tid] = v0; row[tid + 256] = v1;
    red[tid] = v0 + v1;
    __syncthreads();
    for (int s = 128; s; s >>= 1) { if (tid < s) red[tid] += red[tid + s]; __syncthreads(); }
    float mu = red[0] * (1.0f / 512.0f);
    __syncthreads();
    float d0 = row[tid] - mu, d1 = row[tid + 256] - mu;
    red[tid] = d0 * d0 + d1 * d1;
    __syncthreads();
    for (int s = 128; s; s >>= 1) { if (tid < s) red[tid] += red[tid + s]; __syncthreads(); }
    float rstd = rsqrtf(red[0] * (1.0f / 512.0f) + LNEPS);
    x[r * 512 + tid]       = d0 * rstd * g[tid]       + bb[tid];
    x[r * 512 + tid + 256] = d1 * rstd * g[tid + 256] + bb[tid + 256];
}

__global__ void rowmax_kernel(const float* __restrict__ x, float* __restrict__ outr, int L) {
    int b = blockIdx.x, c = threadIdx.x; // 512 threads
    float m = -INFINITY;
    for (int l = 0; l < L; l++) m = fmaxf(m, x[(size_t)(b * L + l) * DM + c]);
    outr[b * DM + c] = m;
}

__global__ void proj_kernel(const float* __restrict__ red, const float* __restrict__ pw,
                            const float* __restrict__ pb, float* __restrict__ out) {
    int w = threadIdx.x >> 5, lane = threadIdx.x & 31; // 16 warps
    int b = w >> 1, o = w & 1;
    float acc = 0.0f;
    for (int c = lane; c < DM; c += 32) acc += red[b * DM + c] * pw[o * DM + c];
    #pragma unroll
    for (int s = 16; s; s >>= 1) acc += __shfl_xor_sync(0xffffffffu, acc, s);
    if (lane == 0) out[b * 2 + o] = acc + pb[o];
}

// ---------------- host ----------------
extern "C" void kernel_launch(void* const* d_in, const int* in_sizes, int n_in,
                              void* d_out, int out_size) {
    (void)n_in; (void)out_size;
    const float* x_enc = (const float*)d_in[0];
    const float* tok_w = (const float*)d_in[1];
    const float *Wq, *Wk, *Wv, *Wo, *bq, *bk, *bv, *bo;
    if (in_sizes[5] > 10000) { // dict order: Wq,Wk,Wv,Wo,bq,bk,bv,bo
        Wq = (const float*)d_in[2]; Wk = (const float*)d_in[3];
        Wv = (const float*)d_in[4]; Wo = (const float*)d_in[5];
        bq = (const float*)d_in[6]; bk = (const float*)d_in[7];
        bv = (const float*)d_in[8]; bo = (const float*)d_in[9];
    } else {                   // signature order: Wq,Wk,Wv,bq,bk,bv,Wo,bo
        Wq = (const float*)d_in[2]; Wk = (const float*)d_in[3];
        Wv = (const float*)d_in[4]; bq = (const float*)d_in[5];
        bk = (const float*)d_in[6]; bv = (const float*)d_in[7];
        Wo = (const float*)d_in[8]; bo = (const float*)d_in[9];
    }
    const float* W1   = (const float*)d_in[10];
    const float* b1   = (const float*)d_in[11];
    const float* W2   = (const float*)d_in[12];
    const float* b2   = (const float*)d_in[13];
    const float* ln1g = (const float*)d_in[14];
    const float* ln1b = (const float*)d_in[15];
    const float* ln2g = (const float*)d_in[16];
    const float* ln2b = (const float*)d_in[17];
    const float* dcw  = (const float*)d_in[18];
    const float* dcb  = (const float*)d_in[19];
    const float* bng  = (const float*)d_in[20];
    const float* bnb  = (const float*)d_in[21];
    const float* lnfg = (const float*)d_in[22];
    const float* lnfb = (const float*)d_in[23];
    const float* pw   = (const float*)d_in[24];
    const float* pb   = (const float*)d_in[25];

    float *x, *q, *k, *v, *o, *t1, *t2, *Mb, *vm, *upd, *redb;
    int *idxb, *topb;
    cudaGetSymbolAddress((void**)&x,   g_x);
    cudaGetSymbolAddress((void**)&q,   g_q);
    cudaGetSymbolAddress((void**)&k,   g_k);
    cudaGetSymbolAddress((void**)&v,   g_v);
    cudaGetSymbolAddress((void**)&o,   g_o);
    cudaGetSymbolAddress((void**)&t1,  g_t1);
    cudaGetSymbolAddress((void**)&t2,  g_t2);
    cudaGetSymbolAddress((void**)&Mb,  g_M);
    cudaGetSymbolAddress((void**)&vm,  g_vm);
    cudaGetSymbolAddress((void**)&upd, g_upd);
    cudaGetSymbolAddress((void**)&redb,g_red);
    cudaGetSymbolAddress((void**)&idxb,g_idx);
    cudaGetSymbolAddress((void**)&topb,g_top);

    embed_kernel<<<(B_*SEQ*DM + 255) / 256, 256>>>(x_enc, tok_w, x);

    int L = SEQ;
    for (int i = 0; i < NL; i++) {
        int Mrows = B_ * L;
        dim3 gg(DM / 128, Mrows / 128);
        gemm_kernel<<<gg, 256>>>(x, Wq + i*DM*DM, bq + i*DM, q, Mrows, DM, DM, 0);
        gemm_kernel<<<gg, 256>>>(x, Wk + i*DM*DM, bk + i*DM, k, Mrows, DM, DM, 0);
        gemm_kernel<<<gg, 256>>>(x, Wv + i*DM*DM, bv + i*DM, v, Mrows, DM, DM, 0);

        // U = min(5*ceil(ln L), L)
        int U = 5 * (int)ceil(log((double)L));
        if (U > L) U = L;

        // Key chain (modern JAX, threefry_partitionable=True):
        //   layer_key = fold_in(key(42), i)        = tf2x32((0,42), (0,i))
        //   (k1, k2)  = foldlike_split(layer_key)  : child_j = tf2x32(layer_key, (0,j))
        //   randint lower_bits use k2 = child 1; multiplier=0 (pow2 span) -> idx = bits(k2) % L
        unsigned f0, f1, c0, c1;
        tf2x32(0u, 42u, 0u, (unsigned)i, &f0, &f1);
        tf2x32(f0, f1, 0u, 1u, &c0, &c1);   // split child 1

        idx_kernel<<<(L*U + 255) / 256, 256>>>(idxb, L, U, c0, c1);
        m_kernel<<<(B_*NH*L*32 + 127) / 128, 128>>>(q, k, idxb, Mb, L, U);
        topk_kernel<<<B_*NH, 256>>>(Mb, topb, L, U);
        vmean_kernel<<<B_*NH, 64>>>(v, vm, L);
        attn_kernel<<<B_*NH*U, 128>>>(q, k, v, topb, upd, L, U);
        oinit_kernel<<<(B_*L*DM + 255) / 256, 256>>>(o, vm, L);
        scatter_kernel<<<B_*NH*U, 64>>>(o, upd, topb, L, U);

        gemm_kernel<<<gg, 256>>>(o, Wo + i*DM*DM, bo + i*DM, t1, Mrows, DM, DM, 0);
        addln_kernel<<<Mrows, 256>>>(x, t1, ln1g + i*DM, ln1b + i*DM);
        gemm_kernel<<<gg, 256>>>(x, W1 + i*DM*DM, b1 + i*DM, t1, Mrows, DM, DM, 1);
        gemm_kernel<<<gg, 256>>>(t1, W2 + i*DM*DM, b2 + i*DM, t2, Mrows, DM, DM, 0);
        addln_kernel<<<Mrows, 256>>>(x, t2, ln2g + i*DM, ln2b + i*DM);

        if (i < NL - 1) {
            convgemm_kernel<<<gg, 256>>>(x, dcw + (size_t)i*DM*DM*3, dcb + i*DM,
                                         bng + i*DM, bnb + i*DM, t1, L);
            int Lout = L / 2;
            pool_kernel<<<(B_*Lout*DM + 255) / 256, 256>>>(t1, x, L);
            L = Lout;
        }
    }

    addln_kernel<<<B_*L, 256>>>(x, (const float*)nullptr, lnfg, lnfb);
    rowmax_kernel<<<B_, 512>>>(x, redb, L);
    proj_kernel<<<1, 512>>>(redb, pw, pb, (float*)d_out);
}

// round 9
// speedup vs baseline: 1.3165x; 1.0422x over previous
#include <cuda_runtime.h>
#include <math.h>

#define B_ 8
#define SEQ 2048
#define DM 512
#define NH 8
#define DH 64
#define NL 3
#define UMAX 40
#define LNEPS 1e-5f

// ---------------- scratch (device globals; no allocation allowed) ----------------
__device__ float g_x [B_*SEQ*DM];
__device__ float g_q [B_*SEQ*DM];
__device__ float g_k [B_*SEQ*DM];
__device__ float g_v [B_*SEQ*DM];
__device__ float g_o [B_*SEQ*DM];
__device__ float g_t1[B_*SEQ*DM];
__device__ float g_t2[B_*SEQ*DM];
__device__ float g_M [B_*NH*SEQ];
__device__ int   g_idx[SEQ*UMAX];
__device__ int   g_top[B_*NH*UMAX];
__device__ float g_vm [B_*NH*DH];
__device__ float g_upd[B_*NH*UMAX*DH];
__device__ float g_red[B_*DM];

// ---------------- threefry2x32 (JAX-compatible) ----------------
__host__ __device__ __forceinline__ void tf2x32(unsigned k0, unsigned k1,
                                                unsigned x0, unsigned x1,
                                                unsigned* o0, unsigned* o1) {
    unsigned ks[3] = {k0, k1, k0 ^ k1 ^ 0x1BD11BDAu};
    x0 += ks[0]; x1 += ks[1];
    const int R0[4] = {13,15,26,6};
    const int R1[4] = {17,29,16,24};
    #pragma unroll
    for (int g = 0; g < 5; g++) {
        #pragma unroll
        for (int q = 0; q < 4; q++) {
            int r = (g & 1) ? R1[q] : R0[q];
            x0 += x1;
            x1 = (x1 << r) | (x1 >> (32 - r));
            x1 ^= x0;
        }
        x0 += ks[(g + 1) % 3];
        x1 += ks[(g + 2) % 3] + (unsigned)(g + 1);
    }
    *o0 = x0; *o1 = x1;
}

// Partitionable threefry random_bits: element f -> counter (0, f); draw = o0 ^ o1.
// randint pow2 span: idx = bits(k2) % L, k2 = foldlike_split(key)[1] (host-side).
__global__ void idx_kernel(int* __restrict__ idx, int L, int U, unsigned k0, unsigned k1) {
    int f = blockIdx.x * blockDim.x + threadIdx.x;
    if (f >= L * U) return;
    unsigned o0, o1;
    tf2x32(k0, k1, 0u, (unsigned)f, &o0, &o1);
    idx[f] = (int)((o0 ^ o1) % (unsigned)L);
}

// ---------------- token embedding + positional encoding ----------------
__global__ void embed_kernel(const float* __restrict__ xe, const float* __restrict__ tw,
                             float* __restrict__ out) {
    int i = blockIdx.x * blockDim.x + threadIdx.x;
    if (i >= B_ * SEQ * DM) return;
    int c = i % DM;
    int l = (i / DM) % SEQ;
    int b = i / (DM * SEQ);
    int lm = (l == 0) ? SEQ - 1 : l - 1;
    int lp = (l == SEQ - 1) ? 0 : l + 1;
    float v = tw[c*3+0]*xe[b*SEQ+lm] + tw[c*3+1]*xe[b*SEQ+l] + tw[c*3+2]*xe[b*SEQ+lp];
    int i2 = c >> 1;
    float div = expf((float)(2*i2) * (-9.210340371976184f / 512.0f));
    float arg = (float)l * div;
    v += (c & 1) ? cosf(arg) : sinf(arg);
    out[i] = v;
}

// ---------------- SGEMM 128x128 tile, 8x8 microtile, double-buffered ----------------
#define SST 132  // padded smem stride (floats); 132*4B is 16B-aligned
__device__ __forceinline__ void gemm_body(
    const float* __restrict__ A, const float* __restrict__ W,
    const float* __restrict__ bias, float* __restrict__ C,
    int M, int N, int K, int act)
{
    __shared__ float As[2][16][SST];
    __shared__ float Ws[2][16][SST];
    int bm = blockIdx.y * 128, bn = blockIdx.x * 128;
    int tid = threadIdx.x;
    int tx = tid & 15, ty = tid >> 4;
    int lr = tid >> 2;          // 0..63
    int lc = (tid & 3) << 2;    // 0,4,8,12
    const float* pa0 = A + (size_t)(bm + lr) * K + lc;
    const float* pa1 = A + (size_t)(bm + lr + 64) * K + lc;
    const float* pw0 = W + (size_t)(bn + lr) * K + lc;
    const float* pw1 = W + (size_t)(bn + lr + 64) * K + lc;
    float acc[8][8] = {};
    {
        float4 a0 = *(const float4*)pa0;
        float4 a1 = *(const float4*)pa1;
        float4 w0 = *(const float4*)pw0;
        float4 w1 = *(const float4*)pw1;
        As[0][lc+0][lr]    = a0.x; As[0][lc+1][lr]    = a0.y; As[0][lc+2][lr]    = a0.z; As[0][lc+3][lr]    = a0.w;
        As[0][lc+0][lr+64] = a1.x; As[0][lc+1][lr+64] = a1.y; As[0][lc+2][lr+64] = a1.z; As[0][lc+3][lr+64] = a1.w;
        Ws[0][lc+0][lr]    = w0.x; Ws[0][lc+1][lr]    = w0.y; Ws[0][lc+2][lr]    = w0.z; Ws[0][lc+3][lr]    = w0.w;
        Ws[0][lc+0][lr+64] = w1.x; Ws[0][lc+1][lr+64] = w1.y; Ws[0][lc+2][lr+64] = w1.z; Ws[0][lc+3][lr+64] = w1.w;
    }
    __syncthreads();
    int buf = 0;
    for (int k0 = 0; k0 < K; k0 += 16) {
        float4 a0n, a1n, w0n, w1n;
        bool pf = (k0 + 16) < K;
        if (pf) {
            a0n = *(const float4*)(pa0 + k0 + 16);
            a1n = *(const float4*)(pa1 + k0 + 16);
            w0n = *(const float4*)(pw0 + k0 + 16);
            w1n = *(const float4*)(pw1 + k0 + 16);
        }
        #pragma unroll
        for (int kk = 0; kk < 16; kk++) {
            float a[8], w[8];
            *(float4*)(a)     = *(const float4*)&As[buf][kk][ty << 2];
            *(float4*)(a + 4) = *(const float4*)&As[buf][kk][64 + (ty << 2)];
            *(float4*)(w)     = *(const float4*)&Ws[buf][kk][tx << 2];
            *(float4*)(w + 4) = *(const float4*)&Ws[buf][kk][64 + (tx << 2)];
            #pragma unroll
            for (int i = 0; i < 8; i++)
                #pragma unroll
                for (int j = 0; j < 8; j++)
                    acc[i][j] += a[i] * w[j];
        }
        if (pf) {
            int nb = buf ^ 1;
            As[nb][lc+0][lr]    = a0n.x; As[nb][lc+1][lr]    = a0n.y; As[nb][lc+2][lr]    = a0n.z; As[nb][lc+3][lr]    = a0n.w;
            As[nb][lc+0][lr+64] = a1n.x; As[nb][lc+1][lr+64] = a1n.y; As[nb][lc+2][lr+64] = a1n.z; As[nb][lc+3][lr+64] = a1n.w;
            Ws[nb][lc+0][lr]    = w0n.x; Ws[nb][lc+1][lr]    = w0n.y; Ws[nb][lc+2][lr]    = w0n.z; Ws[nb][lc+3][lr]    = w0n.w;
            Ws[nb][lc+0][lr+64] = w1n.x; Ws[nb][lc+1][lr+64] = w1n.y; Ws[nb][lc+2][lr+64] = w1n.z; Ws[nb][lc+3][lr+64] = w1n.w;
        }
        __syncthreads();
        buf ^= 1;
    }
    #pragma unroll
    for (int i = 0; i < 8; i++) {
        int m = bm + ((i < 4) ? ((ty << 2) + i) : (64 + (ty << 2) + i - 4));
        #pragma unroll
        for (int jh = 0; jh < 2; jh++) {
            int n = bn + jh * 64 + (tx << 2);
            float4 o;
            o.x = acc[i][jh*4+0] + bias[n+0];
            o.y = acc[i][jh*4+1] + bias[n+1];
            o.z = acc[i][jh*4+2] + bias[n+2];
            o.w = acc[i][jh*4+3] + bias[n+3];
            if (act) {
                o.x = 0.5f * o.x * (1.0f + erff(o.x * 0.7071067811865475f));
                o.y = 0.5f * o.y * (1.0f + erff(o.y * 0.7071067811865475f));
                o.z = 0.5f * o.z * (1.0f + erff(o.z * 0.7071067811865475f));
                o.w = 0.5f * o.w * (1.0f + erff(o.w * 0.7071067811865475f));
            }
            *(float4*)(C + (size_t)m * N + n) = o;
        }
    }
}

__global__ __launch_bounds__(256, 2) void gemm_kernel(
    const float* __restrict__ A, const float* __restrict__ W,
    const float* __restrict__ bias, float* __restrict__ C,
    int M, int N, int K, int act)
{
    gemm_body(A, W, bias, C, M, N, K, act);
}

// fused QKV: blockIdx.z selects projection; A tile shared via L2
__global__ __launch_bounds__(256, 2) void qkv_kernel(
    const float* __restrict__ A,
    const float* __restrict__ Wq, const float* __restrict__ Wk, const float* __restrict__ Wv,
    const float* __restrict__ bq, const float* __restrict__ bk, const float* __restrict__ bv,
    float* __restrict__ q, float* __restrict__ k, float* __restrict__ v,
    int M, int K)
{
    const float* W; const float* b; float* C;
    if (blockIdx.z == 0)      { W = Wq; b = bq; C = q; }
    else if (blockIdx.z == 1) { W = Wk; b = bk; C = k; }
    else                      { W = Wv; b = bv; C = v; }
    gemm_body(A, W, b, C, M, DM, K, 0);
}

// ---------------- distil conv as GEMM (K=3*DM, circular pad) + BN-affine + ELU ----------------
__global__ __launch_bounds__(256, 2) void convgemm_kernel(
    const float* __restrict__ X, const float* __restrict__ Wc,
    const float* __restrict__ cb, const float* __restrict__ gg,
    const float* __restrict__ be, float* __restrict__ C, int L)
{
    __shared__ float As[2][16][SST];
    __shared__ float Ws[2][16][SST];
    int bm = blockIdx.y * 128, bn = blockIdx.x * 128;
    int tid = threadIdx.x;
    int tx = tid & 15, ty = tid >> 4;
    int lr = tid >> 2;
    int lc = (tid & 3) << 2;
    int m0 = bm + lr,      b0 = m0 / L, l0 = m0 % L;
    int m1 = bm + lr + 64, b1 = m1 / L, l1 = m1 % L;
    int n0 = bn + lr, n1 = bn + lr + 64;
    float acc[8][8] = {};

    auto loadk = [&](int k0, float4& a0, float4& a1, float4& w0, float4& w1) {
        int kk = k0 + lc;
        int j = kk / DM;            // conv tap 0..2 (float4 never crosses tap boundary)
        int i0 = kk - j * DM;
        int ls0 = l0 - 1 + j; if (ls0 < 0) ls0 += L; else if (ls0 >= L) ls0 -= L;
        int ls1 = l1 - 1 + j; if (ls1 < 0) ls1 += L; else if (ls1 >= L) ls1 -= L;
        a0 = *(const float4*)(X + (size_t)(b0 * L + ls0) * DM + i0);
        a1 = *(const float4*)(X + (size_t)(b1 * L + ls1) * DM + i0);
        w0.x = Wc[((size_t)n0 * DM + i0 + 0) * 3 + j];
        w0.y = Wc[((size_t)n0 * DM + i0 + 1) * 3 + j];
        w0.z = Wc[((size_t)n0 * DM + i0 + 2) * 3 + j];
        w0.w = Wc[((size_t)n0 * DM + i0 + 3) * 3 + j];
        w1.x = Wc[((size_t)n1 * DM + i0 + 0) * 3 + j];
        w1.y = Wc[((size_t)n1 * DM + i0 + 1) * 3 + j];
        w1.z = Wc[((size_t)n1 * DM + i0 + 2) * 3 + j];
        w1.w = Wc[((size_t)n1 * DM + i0 + 3) * 3 + j];
    };
    auto stores = [&](int nb, const float4& a0, const float4& a1,
                      const float4& w0, const float4& w1) {
        As[nb][lc+0][lr]    = a0.x; As[nb][lc+1][lr]    = a0.y; As[nb][lc+2][lr]    = a0.z; As[nb][lc+3][lr]    = a0.w;
        As[nb][lc+0][lr+64] = a1.x; As[nb][lc+1][lr+64] = a1.y; As[nb][lc+2][lr+64] = a1.z; As[nb][lc+3][lr+64] = a1.w;
        Ws[nb][lc+0][lr]    = w0.x; Ws[nb][lc+1][lr]    = w0.y; Ws[nb][lc+2][lr]    = w0.z; Ws[nb][lc+3][lr]    = w0.w;
        Ws[nb][lc+0][lr+64] = w1.x; Ws[nb][lc+1][lr+64] = w1.y; Ws[nb][lc+2][lr+64] = w1.z; Ws[nb][lc+3][lr+64] = w1.w;
    };

    {
        float4 a0, a1, w0, w1;
        loadk(0, a0, a1, w0, w1);
        stores(0, a0, a1, w0, w1);
    }
    __syncthreads();
    int buf = 0;
    for (int k0 = 0; k0 < 3 * DM; k0 += 16) {
        float4 a0n, a1n, w0n, w1n;
        bool pf = (k0 + 16) < 3 * DM;
        if (pf) loadk(k0 + 16, a0n, a1n, w0n, w1n);
        #pragma unroll
        for (int kk2 = 0; kk2 < 16; kk2++) {
            float a[8], w[8];
            *(float4*)(a)     = *(const float4*)&As[buf][kk2][ty << 2];
            *(float4*)(a + 4) = *(const float4*)&As[buf][kk2][64 + (ty << 2)];
            *(float4*)(w)     = *(const float4*)&Ws[buf][kk2][tx << 2];
            *(float4*)(w + 4) = *(const float4*)&Ws[buf][kk2][64 + (tx << 2)];
            #pragma unroll
            for (int i = 0; i < 8; i++)
                #pragma unroll
                for (int jj = 0; jj < 8; jj++)
                    acc[i][jj] += a[i] * w[jj];
        }
        if (pf) stores(buf ^ 1, a0n, a1n, w0n, w1n);
        __syncthreads();
        buf ^= 1;
    }
    const float invs = 0.9999950000374997f; // 1/sqrt(1+1e-5)
    #pragma unroll
    for (int i = 0; i < 8; i++) {
        int m = bm + ((i < 4) ? ((ty << 2) + i) : (64 + (ty << 2) + i - 4));
        #pragma unroll
        for (int jh = 0; jh < 2; jh++) {
            int n = bn + jh * 64 + (tx << 2);
            float4 o;
            float* po = &o.x;
            #pragma unroll
            for (int c4 = 0; c4 < 4; c4++) {
                float v = (acc[i][jh*4+c4] + cb[n+c4]) * invs * gg[n+c4] + be[n+c4];
                po[c4] = v > 0.0f ? v : expm1f(v);
            }
            *(float4*)(C + (size_t)m * DM + n) = o;
        }
    }
}

// maxpool kernel=3 stride=2 pad=1 (-inf identity) along L
__global__ void pool_kernel(const float* __restrict__ Y, float* __restrict__ X, int Lin) {
    int Lout = Lin >> 1;
    int i = blockIdx.x * blockDim.x + threadIdx.x;
    if (i >= B_ * Lout * DM) return;
    int c = i % DM;
    int lp = (i / DM) % Lout;
    int b = i / (DM * Lout);
    float mv = -INFINITY;
    #pragma unroll
    for (int j = 0; j < 3; j++) {
        int l = 2 * lp - 1 + j;
        if (l >= 0 && l < Lin) mv = fmaxf(mv, Y[(size_t)(b * Lin + l) * DM + c]);
    }
    X[(size_t)(b * Lout + lp) * DM + c] = mv;
}

// ---------------- sparsity measure M[b,h,l] = max_u qk - mean_u qk ----------------
__global__ void m_kernel(const float* __restrict__ q, const float* __restrict__ k,
                         const int* __restrict__ idx, float* __restrict__ Mout,
                         int L, int U) {
    int wid = (blockIdx.x * blockDim.x + threadIdx.x) >> 5;
    int lane = threadIdx.x & 31;
    if (wid >= B_ * NH * L) return;
    int l = wid % L;
    int bh = wid / L;
    int h = bh % NH, b = bh / NH;
    const float* qp = q + (size_t)(b * L + l) * DM + h * DH;
    float q0 = qp[lane], q1 = qp[lane + 32];
    float mx = -INFINITY, sum = 0.0f;
    for (int u = 0; u < U; u++) {
        int ki = idx[l * U + u];
        const float* kp = k + (size_t)(b * L + ki) * DM + h * DH;
        float p = q0 * kp[lane] + q1 * kp[lane + 32];
        #pragma unroll
        for (int off = 16; off; off >>= 1) p += __shfl_xor_sync(0xffffffffu, p, off);
        mx = fmaxf(mx, p);
        sum += p;
    }
    if (lane == 0) Mout[bh * L + l] = mx - sum / (float)U;
}

// ---------------- top-U selection (value desc, tie -> smaller index) ----------------
__global__ void topk_kernel(const float* __restrict__ Mv, int* __restrict__ top, int L, int U) {
    __shared__ float sm[2048];
    __shared__ float rv[256];
    __shared__ int   ri[256];
    int bh = blockIdx.x, tid = threadIdx.x;
    const float* row = Mv + bh * L;
    for (int l = tid; l < L; l += 256) sm[l] = row[l];
    __syncthreads();
    for (int it = 0; it < U; it++) {
        float bv = -INFINITY; int bi = 0x7fffffff;
        for (int l = tid; l < L; l += 256) {
            float v = sm[l];
            if (v > bv || (v == bv && l < bi)) { bv = v; bi = l; }
        }
        rv[tid] = bv; ri[tid] = bi;
        __syncthreads();
        for (int s = 128; s > 0; s >>= 1) {
            if (tid < s) {
                if (rv[tid+s] > rv[tid] || (rv[tid+s] == rv[tid] && ri[tid+s] < ri[tid])) {
                    rv[tid] = rv[tid+s]; ri[tid] = ri[tid+s];
                }
            }
            __syncthreads();
        }
        if (tid == 0) { top[bh * U + it] = ri[0]; sm[ri[0]] = -INFINITY; }
        __syncthreads();
    }
}

// 256 threads: 4 partial sums per d, then smem reduce
__global__ void vmean_kernel(const float* __restrict__ v, float* __restrict__ vm, int L) {
    __shared__ float sred[256];
    int bh = blockIdx.x;
    int h = bh % NH, b = bh / NH;
    int tid = threadIdx.x;
    int d = tid & 63, part = tid >> 6;    // 4 parts
    int chunk = L >> 2;
    float acc = 0.0f;
    for (int l = part * chunk; l < (part + 1) * chunk; l++)
        acc += v[(size_t)(b * L + l) * DM + h * DH + d];
    sred[tid] = acc;
    __syncthreads();
    if (tid < 128) sred[tid] += sred[tid + 128];
    __syncthreads();
    if (tid < 64) vm[bh * DH + tid] = (sred[tid] + sred[tid + 64]) / (float)L;
}

// ---------------- full softmax attention for the U selected queries ----------------
__global__ void attn_kernel(const float* __restrict__ q, const float* __restrict__ k,
                            const float* __restrict__ v, const int* __restrict__ top,
                            float* __restrict__ upd, int L, int U) {
    __shared__ float qs[64];
    __shared__ float s[2048];
    __shared__ float red[128];
    int bhu = blockIdx.x;
    int u = bhu % U;
    int bh = bhu / U;
    int h = bh % NH, b = bh / NH;
    int tid = threadIdx.x; // 128
    int lq = top[bh * U + u];
    if (tid < 64) qs[tid] = q[(size_t)(b * L + lq) * DM + h * DH + tid];
    __syncthreads();
    float lmax = -INFINITY;
    const float4* qs4 = (const float4*)qs;
    for (int l = tid; l < L; l += 128) {
        const float4* kp4 = (const float4*)(k + (size_t)(b * L + l) * DM + h * DH);
        float acc = 0.0f;
        #pragma unroll
        for (int d4 = 0; d4 < 16; d4++) {
            float4 kk = kp4[d4], qq = qs4[d4];
            acc += qq.x*kk.x + qq.y*kk.y + qq.z*kk.z + qq.w*kk.w;
        }
        acc *= 0.125f;
        s[l] = acc;
        lmax = fmaxf(lmax, acc);
    }
    red[tid] = lmax; __syncthreads();
    for (int st = 64; st; st >>= 1) { if (tid < st) red[tid] = fmaxf(red[tid], red[tid+st]); __syncthreads(); }
    float mx = red[0]; __syncthreads();
    float lsum = 0.0f;
    for (int l = tid; l < L; l += 128) { float e = expf(s[l] - mx); s[l] = e; lsum += e; }
    red[tid] = lsum; __syncthreads();
    for (int st = 64; st; st >>= 1) { if (tid < st) red[tid] += red[tid+st]; __syncthreads(); }
    float ssum = red[0]; __syncthreads();
    int d = tid & 63, half = tid >> 6;
    int l0 = half * (L >> 1), l1 = l0 + (L >> 1);
    float acc = 0.0f;
    for (int l = l0; l < l1; l++) acc += s[l] * v[(size_t)(b * L + l) * DM + h * DH + d];
    red[tid] = acc; __syncthreads();
    if (tid < 64) upd[(size_t)(bh * U + u) * DH + tid] = (red[tid] + red[tid + 64]) / ssum;
}

__global__ void oinit_kernel(float* __restrict__ o, const float* __restrict__ vm, int L) {
    int i = blockIdx.x * blockDim.x + threadIdx.x;
    if (i >= B_ * L * DM) return;
    int c = i % DM;
    int b = i / (DM * L);
    o[i] = vm[(b * NH + (c >> 6)) * DH + (c & 63)];
}

__global__ void scatter_kernel(float* __restrict__ o, const float* __restrict__ upd,
                               const int* __restrict__ top, int L, int U) {
    int bhu = blockIdx.x, d = threadIdx.x;
    int u = bhu % U;
    int bh = bhu / U;
    int h = bh % NH, b = bh / NH;
    int l = top[bh * U + u];
    o[(size_t)(b * L + l) * DM + h * DH + d] = upd[(size_t)(bh * U + u) * DH + d];
}

// ---------------- x = LayerNorm(x + t) (t may be null) ----------------
__global__ void addln_kernel(float* __restrict__ x, const float* __restrict__ t,
                             const float* __restrict__ g, const float* __restrict__ bb) {
    __shared__ float row[512];
    __shared__ float red[256];
    size_t r = blockIdx.x;
    int tid = threadIdx.x;
    float v0 = x[r * 512 + tid]       + (t ? t[r * 512 + tid]       : 0.0f);
    float v1 = x[r * 512 + tid + 256] + (t ? t[r * 512 + tid + 256] : 0.0f);
    row[tid] = v0; row[tid + 256] = v1;
    red[tid] = v0 + v1;
    __syncthreads();
    for (int s = 128; s; s >>= 1) { if (tid < s) red[tid] += red[tid + s]; __syncthreads(); }
    float mu = red[0] * (1.0f / 512.0f);
    __syncthreads();
    float d0 = row[tid] - mu, d1 = row[tid + 256] - mu;
    red[tid] = d0 * d0 + d1 * d1;
    __syncthreads();
    for (int s = 128; s; s >>= 1) { if (tid < s) red[tid] += red[tid + s]; __syncthreads(); }
    float rstd = rsqrtf(red[0] * (1.0f / 512.0f) + LNEPS);
    x[r * 512 + tid]       = d0 * rstd * g[tid]       + bb[tid];
    x[r * 512 + tid + 256] = d1 * rstd * g[tid + 256] + bb[tid + 256];
}

__global__ void rowmax_kernel(const float* __restrict__ x, float* __restrict__ outr, int L) {
    int b = blockIdx.x, c = threadIdx.x; // 512 threads
    float m = -INFINITY;
    for (int l = 0; l < L; l++) m = fmaxf(m, x[(size_t)(b * L + l) * DM + c]);
    outr[b * DM + c] = m;
}

__global__ void proj_kernel(const float* __restrict__ red, const float* __restrict__ pw,
                            const float* __restrict__ pb, float* __restrict__ out) {
    int w = threadIdx.x >> 5, lane = threadIdx.x & 31; // 16 warps
    int b = w >> 1, o = w & 1;
    float acc = 0.0f;
    for (int c = lane; c < DM; c += 32) acc += red[b * DM + c] * pw[o * DM + c];
    #pragma unroll
    for (int s = 16; s; s >>= 1) acc += __shfl_xor_sync(0xffffffffu, acc, s);
    if (lane == 0) out[b * 2 + o] = acc + pb[o];
}

// ---------------- host ----------------
extern "C" void kernel_launch(void* const* d_in, const int* in_sizes, int n_in,
                              void* d_out, int out_size) {
    (void)n_in; (void)out_size;
    const float* x_enc = (const float*)d_in[0];
    const float* tok_w = (const float*)d_in[1];
    const float *Wq, *Wk, *Wv, *Wo, *bq, *bk, *bv, *bo;
    if (in_sizes[5] > 10000) { // dict order: Wq,Wk,Wv,Wo,bq,bk,bv,bo
        Wq = (const float*)d_in[2]; Wk = (const float*)d_in[3];
        Wv = (const float*)d_in[4]; Wo = (const float*)d_in[5];
        bq = (const float*)d_in[6]; bk = (const float*)d_in[7];
        bv = (const float*)d_in[8]; bo = (const float*)d_in[9];
    } else {                   // signature order: Wq,Wk,Wv,bq,bk,bv,Wo,bo
        Wq = (const float*)d_in[2]; Wk = (const float*)d_in[3];
        Wv = (const float*)d_in[4]; bq = (const float*)d_in[5];
        bk = (const float*)d_in[6]; bv = (const float*)d_in[7];
        Wo = (const float*)d_in[8]; bo = (const float*)d_in[9];
    }
    const float* W1   = (const float*)d_in[10];
    const float* b1   = (const float*)d_in[11];
    const float* W2   = (const float*)d_in[12];
    const float* b2   = (const float*)d_in[13];
    const float* ln1g = (const float*)d_in[14];
    const float* ln1b = (const float*)d_in[15];
    const float* ln2g = (const float*)d_in[16];
    const float* ln2b = (const float*)d_in[17];
    const float* dcw  = (const float*)d_in[18];
    const float* dcb  = (const float*)d_in[19];
    const float* bng  = (const float*)d_in[20];
    const float* bnb  = (const float*)d_in[21];
    const float* lnfg = (const float*)d_in[22];
    const float* lnfb = (const float*)d_in[23];
    const float* pw   = (const float*)d_in[24];
    const float* pb   = (const float*)d_in[25];

    float *x, *q, *k, *v, *o, *t1, *t2, *Mb, *vm, *upd, *redb;
    int *idxb, *topb;
    cudaGetSymbolAddress((void**)&x,   g_x);
    cudaGetSymbolAddress((void**)&q,   g_q);
    cudaGetSymbolAddress((void**)&k,   g_k);
    cudaGetSymbolAddress((void**)&v,   g_v);
    cudaGetSymbolAddress((void**)&o,   g_o);
    cudaGetSymbolAddress((void**)&t1,  g_t1);
    cudaGetSymbolAddress((void**)&t2,  g_t2);
    cudaGetSymbolAddress((void**)&Mb,  g_M);
    cudaGetSymbolAddress((void**)&vm,  g_vm);
    cudaGetSymbolAddress((void**)&upd, g_upd);
    cudaGetSymbolAddress((void**)&redb,g_red);
    cudaGetSymbolAddress((void**)&idxb,g_idx);
    cudaGetSymbolAddress((void**)&topb,g_top);

    embed_kernel<<<(B_*SEQ*DM + 255) / 256, 256>>>(x_enc, tok_w, x);

    int L = SEQ;
    for (int i = 0; i < NL; i++) {
        int Mrows = B_ * L;
        dim3 gg(DM / 128, Mrows / 128);
        dim3 g3(DM / 128, Mrows / 128, 3);
        qkv_kernel<<<g3, 256>>>(x, Wq + i*DM*DM, Wk + i*DM*DM, Wv + i*DM*DM,
                                bq + i*DM, bk + i*DM, bv + i*DM,
                                q, k, v, Mrows, DM);

        // U = min(5*ceil(ln L), L)
        int U = 5 * (int)ceil(log((double)L));
        if (U > L) U = L;

        // Key chain (modern JAX, threefry_partitionable=True):
        //   layer_key = fold_in(key(42), i)        = tf2x32((0,42), (0,i))
        //   (k1, k2)  = foldlike_split(layer_key)  : child_j = tf2x32(layer_key, (0,j))
        //   randint lower_bits use k2 = child 1; multiplier=0 (pow2 span) -> idx = bits(k2) % L
        unsigned f0, f1, c0, c1;
        tf2x32(0u, 42u, 0u, (unsigned)i, &f0, &f1);
        tf2x32(f0, f1, 0u, 1u, &c0, &c1);   // split child 1

        idx_kernel<<<(L*U + 255) / 256, 256>>>(idxb, L, U, c0, c1);
        m_kernel<<<(B_*NH*L*32 + 127) / 128, 128>>>(q, k, idxb, Mb, L, U);
        topk_kernel<<<B_*NH, 256>>>(Mb, topb, L, U);
        vmean_kernel<<<B_*NH, 256>>>(v, vm, L);
        attn_kernel<<<B_*NH*U, 128>>>(q, k, v, topb, upd, L, U);
        oinit_kernel<<<(B_*L*DM + 255) / 256, 256>>>(o, vm, L);
        scatter_kernel<<<B_*NH*U, 64>>>(o, upd, topb, L, U);

        gemm_kernel<<<gg, 256>>>(o, Wo + i*DM*DM, bo + i*DM, t1, Mrows, DM, DM, 0);
        addln_kernel<<<Mrows, 256>>>(x, t1, ln1g + i*DM, ln1b + i*DM);
        gemm_kernel<<<gg, 256>>>(x, W1 + i*DM*DM, b1 + i*DM, t1, Mrows, DM, DM, 1);
        gemm_kernel<<<gg, 256>>>(t1, W2 + i*DM*DM, b2 + i*DM, t2, Mrows, DM, DM, 0);
        addln_kernel<<<Mrows, 256>>>(x, t2, ln2g + i*DM, ln2b + i*DM);

        if (i < NL - 1) {
            convgemm_kernel<<<gg, 256>>>(x, dcw + (size_t)i*DM*DM*3, dcb + i*DM,
                                         bng + i*DM, bnb + i*DM, t1, L);
            int Lout = L / 2;
            pool_kernel<<<(B_*Lout*DM + 255) / 256, 256>>>(t1, x, L);
            L = Lout;
        }
    }

    addln_kernel<<<B_*L, 256>>>(x, (const float*)nullptr, lnfg, lnfb);
    rowmax_kernel<<<B_, 512>>>(x, redb, L);
    proj_kernel<<<1, 512>>>(redb, pw, pb, (float*)d_out);
}